// round 1
// baseline (speedup 1.0000x reference)
#include <cuda_runtime.h>
#include <math.h>

#define NTOK 6144
#define DV   1024
#define DA   128
#define DC   (DV + DA)   // 1152
#define DH   1024
#define APP  20
#define BANDW 39         // 2*APP - 1
#define BANDP 40         // padded row stride for band storage

// ---------------- scratch (static device globals; no allocation) -------------
__device__ float g_Kv [NTOK * DV];
__device__ float g_Qv [NTOK * DV];
__device__ float g_Vv [NTOK * DV];
__device__ float g_Yv [NTOK * DV];   // att.T @ V (video)
__device__ float g_Yov[NTOK * DV];   // after Wo_v
__device__ float g_Ka [NTOK * DA];
__device__ float g_Qa [NTOK * DA];
__device__ float g_Va [NTOK * DA];
__device__ float g_Ya [NTOK * DA];
__device__ float g_Yoa[NTOK * DA];
__device__ float g_attv[NTOK * BANDP];
__device__ float g_atta[NTOK * BANDP];
__device__ float g_ycomb[NTOK * DC]; // [y_norm | ya_norm]
__device__ float g_h  [NTOK * DH];

// ---------------- GEMM: C[MxNc] = alpha * A[MxK] * B[NcxK]^T (+bias)(relu) ---
// All dims here are multiples of the tile sizes (64/64/16), so no guards.
__global__ void gemm_nt(const float* __restrict__ A, const float* __restrict__ B,
                        float* __restrict__ C, int M, int Nc, int K,
                        int lda, int ldb, int ldc, float alpha,
                        const float* __restrict__ bias, int relu)
{
    __shared__ float As[16][65];
    __shared__ float Bs[16][65];
    const int t  = threadIdx.x;
    const int tx = t & 15, ty = t >> 4;
    const int row0 = blockIdx.y * 64, col0 = blockIdx.x * 64;

    float acc[4][4];
#pragma unroll
    for (int i = 0; i < 4; i++)
#pragma unroll
        for (int j = 0; j < 4; j++) acc[i][j] = 0.f;

    const float* Ap = A + (size_t)row0 * lda;
    const float* Bp = B + (size_t)col0 * ldb;
    const int lr = t >> 2;          // 0..63
    const int lc = (t & 3) * 4;     // 0,4,8,12

    for (int k0 = 0; k0 < K; k0 += 16) {
        float4 av = *reinterpret_cast<const float4*>(Ap + (size_t)lr * lda + k0 + lc);
        float4 bv = *reinterpret_cast<const float4*>(Bp + (size_t)lr * ldb + k0 + lc);
        As[lc + 0][lr] = av.x; As[lc + 1][lr] = av.y;
        As[lc + 2][lr] = av.z; As[lc + 3][lr] = av.w;
        Bs[lc + 0][lr] = bv.x; Bs[lc + 1][lr] = bv.y;
        Bs[lc + 2][lr] = bv.z; Bs[lc + 3][lr] = bv.w;
        __syncthreads();
#pragma unroll
        for (int kk = 0; kk < 16; kk++) {
            float a[4], b[4];
#pragma unroll
            for (int u = 0; u < 4; u++) { a[u] = As[kk][ty * 4 + u]; b[u] = Bs[kk][tx * 4 + u]; }
#pragma unroll
            for (int i = 0; i < 4; i++)
#pragma unroll
                for (int j = 0; j < 4; j++) acc[i][j] = fmaf(a[i], b[j], acc[i][j]);
        }
        __syncthreads();
    }

#pragma unroll
    for (int i = 0; i < 4; i++) {
        const int r = row0 + ty * 4 + i;
#pragma unroll
        for (int j = 0; j < 4; j++) {
            const int c = col0 + tx * 4 + j;
            float v = acc[i][j] * alpha;
            if (bias) v += bias[c];
            if (relu) v = fmaxf(v, 0.f);
            C[(size_t)r * ldc + c] = v;
        }
    }
}

// ---------------- banded logits + softmax: att_band[i][j-i+APP-1] ------------
__global__ void band_att(const float* __restrict__ Q, const float* __restrict__ Km,
                         float* __restrict__ attb, int n, int d)
{
    __shared__ float qs[DV];
    __shared__ float lg[BANDW];
    const int i = blockIdx.x;
    for (int c = threadIdx.x; c < d; c += blockDim.x) qs[c] = Q[(size_t)i * d + c];
    __syncthreads();

    const int j0 = max(i - (APP - 1), 0);
    const int j1 = min(i + (APP - 1), n - 1);
    const int nb = j1 - j0 + 1;
    const int warp = threadIdx.x >> 5, lane = threadIdx.x & 31;
    const int nwarp = blockDim.x >> 5;

    for (int jj = warp; jj < nb; jj += nwarp) {
        const float* kr = Km + (size_t)(j0 + jj) * d;
        float s = 0.f;
        for (int c = lane; c < d; c += 32) s = fmaf(qs[c], kr[c], s);
#pragma unroll
        for (int o = 16; o; o >>= 1) s += __shfl_down_sync(0xffffffffu, s, o);
        if (lane == 0) lg[jj] = s;
    }
    __syncthreads();

    if (threadIdx.x == 0) {
        float m = -1e30f;
        for (int k = 0; k < nb; k++) m = fmaxf(m, lg[k]);
        float ssum = 0.f;
        for (int k = 0; k < nb; k++) { float e = expf(lg[k] - m); lg[k] = e; ssum += e; }
        const float inv = 1.f / ssum;
        for (int k = 0; k < nb; k++) {
            const int j = j0 + k;
            attb[(size_t)i * BANDP + (j - i + (APP - 1))] = lg[k] * inv;
        }
    }
}

// ---------------- y[i] = sum_j att[j][i] * V[j]  (att.T @ V, banded) ---------
__global__ void band_apply(const float* __restrict__ attb, const float* __restrict__ V,
                           float* __restrict__ Y, int n, int d)
{
    __shared__ float w[BANDW];
    const int i = blockIdx.x;
    const int j0 = max(i - (APP - 1), 0);
    const int j1 = min(i + (APP - 1), n - 1);
    const int nb = j1 - j0 + 1;
    if ((int)threadIdx.x < nb) {
        const int j = j0 + threadIdx.x;
        w[threadIdx.x] = attb[(size_t)j * BANDP + (i - j + (APP - 1))];
    }
    __syncthreads();
    for (int c = threadIdx.x; c < d; c += blockDim.x) {
        float acc = 0.f;
        for (int jj = 0; jj < nb; jj++)
            acc = fmaf(w[jj], V[(size_t)(j0 + jj) * d + c], acc);
        Y[(size_t)i * d + c] = acc;
    }
}

// ---------------- residual + layernorm, writes into strided dest -------------
__global__ void ln_res(const float* __restrict__ y, const float* __restrict__ x,
                       const float* __restrict__ g, const float* __restrict__ b,
                       float* __restrict__ dst, int d, int dstride)
{
    __shared__ float sh1[32], sh2[32];
    __shared__ float s_mu, s_rstd;
    const int i = blockIdx.x;
    const int lane = threadIdx.x & 31, wid = threadIdx.x >> 5;
    const int nw = blockDim.x >> 5;

    float sum = 0.f, sq = 0.f;
    for (int c = threadIdx.x; c < d; c += blockDim.x) {
        float v = y[(size_t)i * d + c];
        if (x) v += x[(size_t)i * d + c];
        sum += v; sq = fmaf(v, v, sq);
    }
#pragma unroll
    for (int o = 16; o; o >>= 1) {
        sum += __shfl_down_sync(0xffffffffu, sum, o);
        sq  += __shfl_down_sync(0xffffffffu, sq,  o);
    }
    if (lane == 0) { sh1[wid] = sum; sh2[wid] = sq; }
    __syncthreads();
    if (wid == 0) {
        float s = (lane < nw) ? sh1[lane] : 0.f;
        float q = (lane < nw) ? sh2[lane] : 0.f;
#pragma unroll
        for (int o = 16; o; o >>= 1) {
            s += __shfl_down_sync(0xffffffffu, s, o);
            q += __shfl_down_sync(0xffffffffu, q, o);
        }
        if (lane == 0) {
            const float mu = s / d;
            float var = q / d - mu * mu;
            s_mu = mu;
            s_rstd = rsqrtf(var + 1e-6f);
        }
    }
    __syncthreads();
    const float mu = s_mu, rstd = s_rstd;
    for (int c = threadIdx.x; c < d; c += blockDim.x) {
        float v = y[(size_t)i * d + c];
        if (x) v += x[(size_t)i * d + c];
        dst[(size_t)i * dstride + c] = (v - mu) * rstd * g[c] + b[c];
    }
}

// ---------------- final head: sigmoid(h . kd_w + kd_b) -----------------------
__global__ void head_k(const float* __restrict__ h, const float* __restrict__ w,
                       const float* __restrict__ b, float* __restrict__ out, int d)
{
    __shared__ float sh[32];
    const int i = blockIdx.x;
    const int lane = threadIdx.x & 31, wid = threadIdx.x >> 5;
    const int nw = blockDim.x >> 5;
    float s = 0.f;
    for (int c = threadIdx.x; c < d; c += blockDim.x)
        s = fmaf(h[(size_t)i * d + c], w[c], s);
#pragma unroll
    for (int o = 16; o; o >>= 1) s += __shfl_down_sync(0xffffffffu, s, o);
    if (lane == 0) sh[wid] = s;
    __syncthreads();
    if (wid == 0) {
        float v = (lane < nw) ? sh[lane] : 0.f;
#pragma unroll
        for (int o = 16; o; o >>= 1) v += __shfl_down_sync(0xffffffffu, v, o);
        if (lane == 0) out[i] = 1.f / (1.f + expf(-(v + b[0])));
    }
}

// ---------------- scatter band attention into dense [N, 2N] output ----------
__global__ void scatter_att(const float* __restrict__ attv, const float* __restrict__ atta,
                            float* __restrict__ out, int n)
{
    const int i = blockIdx.x;
    const size_t base = (size_t)n + (size_t)i * 2u * (size_t)n;  // score occupies first n
    const int j0 = max(i - (APP - 1), 0);
    const int j1 = min(i + (APP - 1), n - 1);
    for (int k = threadIdx.x; k <= j1 - j0; k += blockDim.x) {
        const int j = j0 + k;
        const float av = attv[(size_t)i * BANDP + (j - i + (APP - 1))];
        const float aa = atta[(size_t)i * BANDP + (j - i + (APP - 1))];
        out[base + j]     = av;
        out[base + n + j] = aa;
    }
}

// ---------------- launch ------------------------------------------------------
extern "C" void kernel_launch(void* const* d_in, const int* in_sizes, int n_in,
                              void* d_out, int out_size)
{
    const float* x     = (const float*)d_in[0];
    const float* xa    = (const float*)d_in[1];
    // d_in[2]=seq_len, d_in[3]=audio_len (device ints; dims derived from sizes)
    const float* Wk_v  = (const float*)d_in[4];
    const float* Wq_v  = (const float*)d_in[5];
    const float* Wv_v  = (const float*)d_in[6];
    const float* Wo_v  = (const float*)d_in[7];
    const float* Wk_a  = (const float*)d_in[8];
    const float* Wq_a  = (const float*)d_in[9];
    const float* Wv_a  = (const float*)d_in[10];
    const float* Wo_a  = (const float*)d_in[11];
    const float* ka_w  = (const float*)d_in[12];
    const float* ka_b  = (const float*)d_in[13];
    const float* kd_w  = (const float*)d_in[14];
    const float* kd_b  = (const float*)d_in[15];
    const float* ln_y_g  = (const float*)d_in[16];
    const float* ln_y_b  = (const float*)d_in[17];
    const float* ln_ya_g = (const float*)d_in[18];
    const float* ln_ya_b = (const float*)d_in[19];
    const float* ln_ka_g = (const float*)d_in[20];
    const float* ln_ka_b = (const float*)d_in[21];

    const int n = in_sizes[0] / DV;   // 6144

    float *Kv, *Qv, *Vv, *Yv, *Yov, *Ka, *Qa, *Va, *Ya, *Yoa, *attv, *atta, *ycomb, *h;
    cudaGetSymbolAddress((void**)&Kv,  g_Kv);
    cudaGetSymbolAddress((void**)&Qv,  g_Qv);
    cudaGetSymbolAddress((void**)&Vv,  g_Vv);
    cudaGetSymbolAddress((void**)&Yv,  g_Yv);
    cudaGetSymbolAddress((void**)&Yov, g_Yov);
    cudaGetSymbolAddress((void**)&Ka,  g_Ka);
    cudaGetSymbolAddress((void**)&Qa,  g_Qa);
    cudaGetSymbolAddress((void**)&Va,  g_Va);
    cudaGetSymbolAddress((void**)&Ya,  g_Ya);
    cudaGetSymbolAddress((void**)&Yoa, g_Yoa);
    cudaGetSymbolAddress((void**)&attv, g_attv);
    cudaGetSymbolAddress((void**)&atta, g_atta);
    cudaGetSymbolAddress((void**)&ycomb, g_ycomb);
    cudaGetSymbolAddress((void**)&h,   g_h);

    float* out = (float*)d_out;
    const size_t full_elems = (size_t)n + 2ull * (size_t)n * (size_t)n;
    const size_t clear = ((size_t)out_size >= full_elems) ? full_elems : (size_t)out_size;
    cudaMemsetAsync(out, 0, clear * sizeof(float), 0);

    const dim3 gv(DV / 64, n / 64);   // video GEMM grid
    const dim3 ga(DA / 64, n / 64);   // audio GEMM grid

    // --- video branch ---
    gemm_nt<<<gv, 256>>>(x, Wk_v, Kv, n, DV, DV, DV, DV, DV, 1.f,   nullptr, 0);
    gemm_nt<<<gv, 256>>>(x, Wq_v, Qv, n, DV, DV, DV, DV, DV, 0.06f, nullptr, 0);
    gemm_nt<<<gv, 256>>>(x, Wv_v, Vv, n, DV, DV, DV, DV, DV, 1.f,   nullptr, 0);
    band_att  <<<n, 256>>>(Qv, Kv, attv, n, DV);
    band_apply<<<n, 256>>>(attv, Vv, Yv, n, DV);
    gemm_nt<<<gv, 256>>>(Yv, Wo_v, Yov, n, DV, DV, DV, DV, DV, 1.f, nullptr, 0);
    ln_res<<<n, 256>>>(Yov, x, ln_y_g, ln_y_b, ycomb, DV, DC);

    // --- audio branch ---
    gemm_nt<<<ga, 256>>>(xa, Wk_a, Ka, n, DA, DA, DA, DA, DA, 1.f,   nullptr, 0);
    gemm_nt<<<ga, 256>>>(xa, Wq_a, Qa, n, DA, DA, DA, DA, DA, 0.06f, nullptr, 0);
    gemm_nt<<<ga, 256>>>(xa, Wv_a, Va, n, DA, DA, DA, DA, DA, 1.f,   nullptr, 0);
    band_att  <<<n, 128>>>(Qa, Ka, atta, n, DA);
    band_apply<<<n, 128>>>(atta, Va, Ya, n, DA);
    gemm_nt<<<ga, 256>>>(Ya, Wo_a, Yoa, n, DA, DA, DA, DA, DA, 1.f, nullptr, 0);
    ln_res<<<n, 128>>>(Yoa, xa, ln_ya_g, ln_ya_b, ycomb + DV, DA, DC);

    // --- MLP head ---
    gemm_nt<<<dim3(DH / 64, n / 64), 256>>>(ycomb, ka_w, h, n, DH, DC, DC, DC, DH,
                                            1.f, ka_b, 1);
    ln_res<<<n, 256>>>(h, nullptr, ln_ka_g, ln_ka_b, h, DH, DH);
    head_k<<<n, 256>>>(h, kd_w, kd_b, out, DH);

    // --- dense attention output ---
    if ((size_t)out_size >= full_elems)
        scatter_att<<<n, 64>>>(attv, atta, out, n);
}

// round 2
// speedup vs baseline: 2.3336x; 2.3336x over previous
#include <cuda_runtime.h>
#include <math.h>

#define NTOK 6144
#define DV   1024
#define DA   128
#define DC   (DV + DA)   // 1152
#define DH   1024
#define APP  20
#define BANDW 39         // 2*APP - 1
#define BANDP 40         // padded row stride for band storage

// ---------------- scratch (static device globals; no allocation) -------------
__device__ float g_Kv [NTOK * DV];
__device__ float g_Qv [NTOK * DV];
__device__ float g_Vv [NTOK * DV];
__device__ float g_Yv [NTOK * DV];
__device__ float g_Yov[NTOK * DV];
__device__ float g_Ka [NTOK * DA];
__device__ float g_Qa [NTOK * DA];
__device__ float g_Va [NTOK * DA];
__device__ float g_Ya [NTOK * DA];
__device__ float g_Yoa[NTOK * DA];
__device__ float g_attv[NTOK * BANDP];
__device__ float g_atta[NTOK * BANDP];
__device__ float g_ycomb[NTOK * DC];
__device__ float g_h  [NTOK * DH];

// =============================================================================
// SGEMM: C[M x Nc] = alpha * A[M x K] * B[Nc x K]^T (+bias)(relu)
// 128x128 block tile, BK=8, 8x8 per thread, double-buffered smem.
// Requires: M % 128 == 0, Nc % 128 == 0, K % 8 == 0 (true for all calls here).
// =============================================================================
__global__ void __launch_bounds__(256, 2)
sgemm128(const float* __restrict__ A, const float* __restrict__ B,
         float* __restrict__ C, int K,
         int lda, int ldb, int ldc, float alpha,
         const float* __restrict__ bias, int relu)
{
    __shared__ float As[2][8][132];
    __shared__ float Bs[2][8][132];

    const int t    = threadIdx.x;
    const int row0 = blockIdx.y * 128;
    const int col0 = blockIdx.x * 128;

    // loader: each thread loads one float4 of A and one of B per K-slab
    const int lr = t >> 1;           // 0..127 (tile row / tile col)
    const int lk = (t & 1) * 4;      // 0 or 4
    const float* Ap = A + (size_t)(row0 + lr) * lda + lk;
    const float* Bp = B + (size_t)(col0 + lr) * ldb + lk;

    // compute mapping: 16x16 threads, each owns rows {ty*4..+3, 64+ty*4..+3},
    // cols {tx*4..+3, 64+tx*4..+3}
    const int tx = t & 15, ty = t >> 4;

    float acc[8][8];
#pragma unroll
    for (int i = 0; i < 8; i++)
#pragma unroll
        for (int j = 0; j < 8; j++) acc[i][j] = 0.f;

    // preload slab 0
    float4 av = *reinterpret_cast<const float4*>(Ap);
    float4 bv = *reinterpret_cast<const float4*>(Bp);
    int buf = 0;
    As[0][lk + 0][lr] = av.x; As[0][lk + 1][lr] = av.y;
    As[0][lk + 2][lr] = av.z; As[0][lk + 3][lr] = av.w;
    Bs[0][lk + 0][lr] = bv.x; Bs[0][lk + 1][lr] = bv.y;
    Bs[0][lk + 2][lr] = bv.z; Bs[0][lk + 3][lr] = bv.w;
    __syncthreads();

    for (int k0 = 8; k0 <= K; k0 += 8) {
        float4 av2, bv2;
        const bool more = (k0 < K);
        if (more) {
            av2 = *reinterpret_cast<const float4*>(Ap + k0);
            bv2 = *reinterpret_cast<const float4*>(Bp + k0);
        }
#pragma unroll
        for (int kk = 0; kk < 8; kk++) {
            float a[8], b[8];
            *reinterpret_cast<float4*>(&a[0]) = *reinterpret_cast<const float4*>(&As[buf][kk][ty * 4]);
            *reinterpret_cast<float4*>(&a[4]) = *reinterpret_cast<const float4*>(&As[buf][kk][64 + ty * 4]);
            *reinterpret_cast<float4*>(&b[0]) = *reinterpret_cast<const float4*>(&Bs[buf][kk][tx * 4]);
            *reinterpret_cast<float4*>(&b[4]) = *reinterpret_cast<const float4*>(&Bs[buf][kk][64 + tx * 4]);
#pragma unroll
            for (int i = 0; i < 8; i++)
#pragma unroll
                for (int j = 0; j < 8; j++)
                    acc[i][j] = fmaf(a[i], b[j], acc[i][j]);
        }
        if (more) {
            buf ^= 1;
            As[buf][lk + 0][lr] = av2.x; As[buf][lk + 1][lr] = av2.y;
            As[buf][lk + 2][lr] = av2.z; As[buf][lk + 3][lr] = av2.w;
            Bs[buf][lk + 0][lr] = bv2.x; Bs[buf][lk + 1][lr] = bv2.y;
            Bs[buf][lk + 2][lr] = bv2.z; Bs[buf][lk + 3][lr] = bv2.w;
            __syncthreads();
        }
    }

    // epilogue
    float4 bia0 = make_float4(0.f, 0.f, 0.f, 0.f), bia1 = bia0;
    if (bias) {
        bia0 = *reinterpret_cast<const float4*>(bias + col0 + tx * 4);
        bia1 = *reinterpret_cast<const float4*>(bias + col0 + 64 + tx * 4);
    }
#pragma unroll
    for (int i = 0; i < 8; i++) {
        const int r = row0 + ((i < 4) ? (ty * 4 + i) : (64 + ty * 4 + i - 4));
        float4 v0, v1;
        v0.x = acc[i][0] * alpha + bia0.x; v0.y = acc[i][1] * alpha + bia0.y;
        v0.z = acc[i][2] * alpha + bia0.z; v0.w = acc[i][3] * alpha + bia0.w;
        v1.x = acc[i][4] * alpha + bia1.x; v1.y = acc[i][5] * alpha + bia1.y;
        v1.z = acc[i][6] * alpha + bia1.z; v1.w = acc[i][7] * alpha + bia1.w;
        if (relu) {
            v0.x = fmaxf(v0.x, 0.f); v0.y = fmaxf(v0.y, 0.f);
            v0.z = fmaxf(v0.z, 0.f); v0.w = fmaxf(v0.w, 0.f);
            v1.x = fmaxf(v1.x, 0.f); v1.y = fmaxf(v1.y, 0.f);
            v1.z = fmaxf(v1.z, 0.f); v1.w = fmaxf(v1.w, 0.f);
        }
        *reinterpret_cast<float4*>(C + (size_t)r * ldc + col0 + tx * 4)      = v0;
        *reinterpret_cast<float4*>(C + (size_t)r * ldc + col0 + 64 + tx * 4) = v1;
    }
}

// ---------------- banded logits + softmax (float4 dot products) --------------
__global__ void band_att(const float* __restrict__ Q, const float* __restrict__ Km,
                         float* __restrict__ attb, int n, int d)
{
    __shared__ __align__(16) float qs[DV];
    __shared__ float lg[BANDW];
    const int i = blockIdx.x;
    for (int c = threadIdx.x; c < d / 4; c += blockDim.x)
        *reinterpret_cast<float4*>(&qs[c * 4]) =
            *reinterpret_cast<const float4*>(Q + (size_t)i * d + c * 4);
    __syncthreads();

    const int j0 = max(i - (APP - 1), 0);
    const int j1 = min(i + (APP - 1), n - 1);
    const int nb = j1 - j0 + 1;
    const int warp = threadIdx.x >> 5, lane = threadIdx.x & 31;
    const int nwarp = blockDim.x >> 5;

    for (int jj = warp; jj < nb; jj += nwarp) {
        const float* kr = Km + (size_t)(j0 + jj) * d;
        float s = 0.f;
        for (int c = lane; c < d / 4; c += 32) {
            float4 q4 = *reinterpret_cast<const float4*>(&qs[c * 4]);
            float4 k4 = *reinterpret_cast<const float4*>(kr + c * 4);
            s = fmaf(q4.x, k4.x, s); s = fmaf(q4.y, k4.y, s);
            s = fmaf(q4.z, k4.z, s); s = fmaf(q4.w, k4.w, s);
        }
#pragma unroll
        for (int o = 16; o; o >>= 1) s += __shfl_down_sync(0xffffffffu, s, o);
        if (lane == 0) lg[jj] = s;
    }
    __syncthreads();

    if (threadIdx.x == 0) {
        float m = -1e30f;
        for (int k = 0; k < nb; k++) m = fmaxf(m, lg[k]);
        float ssum = 0.f;
        for (int k = 0; k < nb; k++) { float e = expf(lg[k] - m); lg[k] = e; ssum += e; }
        const float inv = 1.f / ssum;
        for (int k = 0; k < nb; k++) {
            const int j = j0 + k;
            attb[(size_t)i * BANDP + (j - i + (APP - 1))] = lg[k] * inv;
        }
    }
}

// ---------------- y[i] = sum_j att[j][i] * V[j]  (att.T @ V, banded) ---------
__global__ void band_apply(const float* __restrict__ attb, const float* __restrict__ V,
                           float* __restrict__ Y, int n, int d)
{
    __shared__ float w[BANDW];
    const int i = blockIdx.x;
    const int j0 = max(i - (APP - 1), 0);
    const int j1 = min(i + (APP - 1), n - 1);
    const int nb = j1 - j0 + 1;
    if ((int)threadIdx.x < nb) {
        const int j = j0 + threadIdx.x;
        w[threadIdx.x] = attb[(size_t)j * BANDP + (i - j + (APP - 1))];
    }
    __syncthreads();
    for (int c = threadIdx.x; c < d / 4; c += blockDim.x) {
        float4 acc = make_float4(0.f, 0.f, 0.f, 0.f);
        for (int jj = 0; jj < nb; jj++) {
            const float wj = w[jj];
            float4 v4 = *reinterpret_cast<const float4*>(V + (size_t)(j0 + jj) * d + c * 4);
            acc.x = fmaf(wj, v4.x, acc.x); acc.y = fmaf(wj, v4.y, acc.y);
            acc.z = fmaf(wj, v4.z, acc.z); acc.w = fmaf(wj, v4.w, acc.w);
        }
        *reinterpret_cast<float4*>(Y + (size_t)i * d + c * 4) = acc;
    }
}

// ---------------- residual + layernorm, writes into strided dest -------------
__global__ void ln_res(const float* __restrict__ y, const float* __restrict__ x,
                       const float* __restrict__ g, const float* __restrict__ b,
                       float* __restrict__ dst, int d, int dstride)
{
    __shared__ float sh1[32], sh2[32];
    __shared__ float s_mu, s_rstd;
    const int i = blockIdx.x;
    const int lane = threadIdx.x & 31, wid = threadIdx.x >> 5;
    const int nw = blockDim.x >> 5;

    float sum = 0.f, sq = 0.f;
    for (int c = threadIdx.x; c < d; c += blockDim.x) {
        float v = y[(size_t)i * d + c];
        if (x) v += x[(size_t)i * d + c];
        sum += v; sq = fmaf(v, v, sq);
    }
#pragma unroll
    for (int o = 16; o; o >>= 1) {
        sum += __shfl_down_sync(0xffffffffu, sum, o);
        sq  += __shfl_down_sync(0xffffffffu, sq,  o);
    }
    if (lane == 0) { sh1[wid] = sum; sh2[wid] = sq; }
    __syncthreads();
    if (wid == 0) {
        float s = (lane < nw) ? sh1[lane] : 0.f;
        float q = (lane < nw) ? sh2[lane] : 0.f;
#pragma unroll
        for (int o = 16; o; o >>= 1) {
            s += __shfl_down_sync(0xffffffffu, s, o);
            q += __shfl_down_sync(0xffffffffu, q, o);
        }
        if (lane == 0) {
            const float mu = s / d;
            float var = q / d - mu * mu;
            s_mu = mu;
            s_rstd = rsqrtf(var + 1e-6f);
        }
    }
    __syncthreads();
    const float mu = s_mu, rstd = s_rstd;
    for (int c = threadIdx.x; c < d; c += blockDim.x) {
        float v = y[(size_t)i * d + c];
        if (x) v += x[(size_t)i * d + c];
        dst[(size_t)i * dstride + c] = (v - mu) * rstd * g[c] + b[c];
    }
}

// ---------------- final head: sigmoid(h . kd_w + kd_b) -----------------------
__global__ void head_k(const float* __restrict__ h, const float* __restrict__ w,
                       const float* __restrict__ b, float* __restrict__ out, int d)
{
    __shared__ float sh[32];
    const int i = blockIdx.x;
    const int lane = threadIdx.x & 31, wid = threadIdx.x >> 5;
    const int nw = blockDim.x >> 5;
    float s = 0.f;
    for (int c = threadIdx.x; c < d; c += blockDim.x)
        s = fmaf(h[(size_t)i * d + c], w[c], s);
#pragma unroll
    for (int o = 16; o; o >>= 1) s += __shfl_down_sync(0xffffffffu, s, o);
    if (lane == 0) sh[wid] = s;
    __syncthreads();
    if (wid == 0) {
        float v = (lane < nw) ? sh[lane] : 0.f;
#pragma unroll
        for (int o = 16; o; o >>= 1) v += __shfl_down_sync(0xffffffffu, v, o);
        if (lane == 0) out[i] = 1.f / (1.f + expf(-(v + b[0])));
    }
}

// ---------------- scatter band attention into dense [N, 2N] output ----------
__global__ void scatter_att(const float* __restrict__ attv, const float* __restrict__ atta,
                            float* __restrict__ out, int n)
{
    const int i = blockIdx.x;
    const size_t base = (size_t)n + (size_t)i * 2u * (size_t)n;
    const int j0 = max(i - (APP - 1), 0);
    const int j1 = min(i + (APP - 1), n - 1);
    for (int k = threadIdx.x; k <= j1 - j0; k += blockDim.x) {
        const int j = j0 + k;
        const float av = attv[(size_t)i * BANDP + (j - i + (APP - 1))];
        const float aa = atta[(size_t)i * BANDP + (j - i + (APP - 1))];
        out[base + j]     = av;
        out[base + n + j] = aa;
    }
}

// ---------------- launch ------------------------------------------------------
extern "C" void kernel_launch(void* const* d_in, const int* in_sizes, int n_in,
                              void* d_out, int out_size)
{
    const float* x     = (const float*)d_in[0];
    const float* xa    = (const float*)d_in[1];
    const float* Wk_v  = (const float*)d_in[4];
    const float* Wq_v  = (const float*)d_in[5];
    const float* Wv_v  = (const float*)d_in[6];
    const float* Wo_v  = (const float*)d_in[7];
    const float* Wk_a  = (const float*)d_in[8];
    const float* Wq_a  = (const float*)d_in[9];
    const float* Wv_a  = (const float*)d_in[10];
    const float* Wo_a  = (const float*)d_in[11];
    const float* ka_w  = (const float*)d_in[12];
    const float* ka_b  = (const float*)d_in[13];
    const float* kd_w  = (const float*)d_in[14];
    const float* kd_b  = (const float*)d_in[15];
    const float* ln_y_g  = (const float*)d_in[16];
    const float* ln_y_b  = (const float*)d_in[17];
    const float* ln_ya_g = (const float*)d_in[18];
    const float* ln_ya_b = (const float*)d_in[19];
    const float* ln_ka_g = (const float*)d_in[20];
    const float* ln_ka_b = (const float*)d_in[21];

    const int n = in_sizes[0] / DV;   // 6144

    float *Kv, *Qv, *Vv, *Yv, *Yov, *Ka, *Qa, *Va, *Ya, *Yoa, *attv, *atta, *ycomb, *h;
    cudaGetSymbolAddress((void**)&Kv,  g_Kv);
    cudaGetSymbolAddress((void**)&Qv,  g_Qv);
    cudaGetSymbolAddress((void**)&Vv,  g_Vv);
    cudaGetSymbolAddress((void**)&Yv,  g_Yv);
    cudaGetSymbolAddress((void**)&Yov, g_Yov);
    cudaGetSymbolAddress((void**)&Ka,  g_Ka);
    cudaGetSymbolAddress((void**)&Qa,  g_Qa);
    cudaGetSymbolAddress((void**)&Va,  g_Va);
    cudaGetSymbolAddress((void**)&Ya,  g_Ya);
    cudaGetSymbolAddress((void**)&Yoa, g_Yoa);
    cudaGetSymbolAddress((void**)&attv, g_attv);
    cudaGetSymbolAddress((void**)&atta, g_atta);
    cudaGetSymbolAddress((void**)&ycomb, g_ycomb);
    cudaGetSymbolAddress((void**)&h,   g_h);

    float* out = (float*)d_out;
    const size_t full_elems = (size_t)n + 2ull * (size_t)n * (size_t)n;
    const size_t clear = ((size_t)out_size >= full_elems) ? full_elems : (size_t)out_size;
    cudaMemsetAsync(out, 0, clear * sizeof(float), 0);

    const dim3 gv(DV / 128, n / 128);   // video GEMMs: (8, 48)
    const dim3 ga(DA / 128, n / 128);   // audio GEMMs: (1, 48)

    // --- video branch ---
    sgemm128<<<gv, 256>>>(x, Wk_v, Kv, DV, DV, DV, DV, 1.f,   nullptr, 0);
    sgemm128<<<gv, 256>>>(x, Wq_v, Qv, DV, DV, DV, DV, 0.06f, nullptr, 0);
    sgemm128<<<gv, 256>>>(x, Wv_v, Vv, DV, DV, DV, DV, 1.f,   nullptr, 0);
    band_att  <<<n, 256>>>(Qv, Kv, attv, n, DV);
    band_apply<<<n, 256>>>(attv, Vv, Yv, n, DV);
    sgemm128<<<gv, 256>>>(Yv, Wo_v, Yov, DV, DV, DV, DV, 1.f, nullptr, 0);
    ln_res<<<n, 256>>>(Yov, x, ln_y_g, ln_y_b, ycomb, DV, DC);

    // --- audio branch ---
    sgemm128<<<ga, 256>>>(xa, Wk_a, Ka, DA, DA, DA, DA, 1.f,   nullptr, 0);
    sgemm128<<<ga, 256>>>(xa, Wq_a, Qa, DA, DA, DA, DA, 0.06f, nullptr, 0);
    sgemm128<<<ga, 256>>>(xa, Wv_a, Va, DA, DA, DA, DA, 1.f,   nullptr, 0);
    band_att  <<<n, 128>>>(Qa, Ka, atta, n, DA);
    band_apply<<<n, 128>>>(atta, Va, Ya, n, DA);
    sgemm128<<<ga, 256>>>(Ya, Wo_a, Yoa, DA, DA, DA, DA, 1.f, nullptr, 0);
    ln_res<<<n, 128>>>(Yoa, xa, ln_ya_g, ln_ya_b, ycomb + DV, DA, DC);

    // --- MLP head ---
    sgemm128<<<dim3(DH / 128, n / 128), 256>>>(ycomb, ka_w, h, DC, DC, DC, DH,
                                               1.f, ka_b, 1);
    ln_res<<<n, 256>>>(h, nullptr, ln_ka_g, ln_ka_b, h, DH, DH);
    head_k<<<n, 256>>>(h, kd_w, kd_b, out, DH);

    // --- dense attention output ---
    if ((size_t)out_size >= full_elems)
        scatter_att<<<n, 64>>>(attv, atta, out, n);
}

// round 5
// speedup vs baseline: 5.2802x; 2.2627x over previous
#include <cuda_runtime.h>
#include <cstdint>
#include <math.h>

#define NTOK 6144
#define DV   1024
#define DA   128
#define DC   (DV + DA)   // 1152
#define DH   1024
#define APP  20
#define BANDW 39
#define BANDP 40

// ---------------- scratch (static device globals; no allocation) -------------
__device__ float g_Kv [NTOK * DV];
__device__ float g_Qv [NTOK * DV];
__device__ float g_Vv [NTOK * DV];
__device__ float g_Yv [NTOK * DV];
__device__ float g_Yov[NTOK * DV];
__device__ float g_Ka [NTOK * DA];
__device__ float g_Qa [NTOK * DA];
__device__ float g_Va [NTOK * DA];
__device__ float g_Ya [NTOK * DA];
__device__ float g_Yoa[NTOK * DA];
__device__ float g_attv[NTOK * BANDP];
__device__ float g_atta[NTOK * BANDP];
__device__ float g_ycomb[NTOK * DC];
__device__ float g_h  [NTOK * DH];

// ======================= helpers =============================================
__device__ __forceinline__ uint32_t smem_u32(const void* p) {
    uint32_t r;
    asm("{ .reg .u64 t; cvta.to.shared.u64 t, %1; cvt.u32.u64 %0, t; }"
        : "=r"(r) : "l"(p));
    return r;
}

__device__ __forceinline__ uint32_t f2tf32(float x) {
    uint32_t r;
    asm("cvt.rna.tf32.f32 %0, %1;" : "=r"(r) : "f"(x));
    return r;
}

#define LDMX4(r0, r1, r2, r3, addr) \
    asm volatile("ldmatrix.sync.aligned.m8n8.x4.shared.b16 {%0,%1,%2,%3}, [%4];" \
                 : "=r"(r0), "=r"(r1), "=r"(r2), "=r"(r3) : "r"(addr))

#define MMA_TF32(c, a0, a1, a2, a3, b0, b1) \
    asm volatile("mma.sync.aligned.m16n8k8.row.col.f32.tf32.tf32.f32 " \
                 "{%0,%1,%2,%3}, {%4,%5,%6,%7}, {%8,%9}, {%0,%1,%2,%3};" \
                 : "+f"((c)[0]), "+f"((c)[1]), "+f"((c)[2]), "+f"((c)[3]) \
                 : "r"(a0), "r"(a1), "r"(a2), "r"(a3), "r"(b0), "r"(b1))

// =============================================================================
// tgemm: C[z] = alpha[z] * A * B[z]^T (+bias)(relu)  via tf32 mma.sync
// CTA tile 128x128, BK=32, double-buffered smem, 8 warps (4M x 2N).
// Requires M%128==0, Nc%128==0, K%32==0.
// smem layout (words, stride 36/row): A0 A1 B0 B1, each 128x36.
// =============================================================================
struct TG {
    const float* A;
    const float *B0, *B1, *B2;
    float *C0, *C1, *C2;
    float a0, a1, a2;
    const float* bias;
    int relu;
    int K, lda, ldb, ldc;
};

#define TILE_BYTES (128 * 36 * 4)           // 18432
#define TG_SMEM    (4 * TILE_BYTES)         // 73728

__global__ void __launch_bounds__(256)
tgemm(TG p)
{
    extern __shared__ char dsm[];
    const int tid  = threadIdx.x;
    const int lane = tid & 31;
    const int wid  = tid >> 5;
    const int wm   = wid & 3;     // 0..3  (32-row slab)
    const int wn   = wid >> 2;    // 0..1  (64-col slab)

    const int row0 = blockIdx.y * 128;
    const int col0 = blockIdx.x * 128;
    const int z = blockIdx.z;
    const float* B = (z == 0) ? p.B0 : (z == 1) ? p.B1 : p.B2;
    float*       C = (z == 0) ? p.C0 : (z == 1) ? p.C1 : p.C2;
    const float alpha = (z == 0) ? p.a0 : (z == 1) ? p.a1 : p.a2;

    const uint32_t sbase = smem_u32(dsm);

    // ---- loader mapping: 2 threads/row, 16 words each --------------------
    const int lrow = tid >> 1;           // 0..127
    const int lcol = (tid & 1) * 16;     // 0 or 16
    const float* Ag = p.A + (size_t)(row0 + lrow) * p.lda + lcol;
    const float* Bg = B   + (size_t)(col0 + lrow) * p.ldb + lcol;
    char* a_st = dsm + ((size_t)lrow * 36 + lcol) * 4;
    char* b_st = a_st + 2 * TILE_BYTES;

    // ---- ldmatrix per-thread addresses -----------------------------------
    // A fragment (16x8): rows m0 + (lane&15), col k0 + (lane>>4)*4
    const uint32_t a_ld0 = sbase +
        (((uint32_t)(wm * 32 + (lane & 15))) * 36u + ((uint32_t)(lane >> 4)) * 4u) * 4u;
    // B fragment (8x8 pair): rows n0 + (lane&7) + (lane>=16?8:0), col ((lane>>3)&1)*4
    const uint32_t b_row = (uint32_t)(wn * 64 + (lane & 7) + ((lane & 16) >> 1));
    const uint32_t b_ld0 = sbase + 2u * TILE_BYTES +
        (b_row * 36u + (((uint32_t)lane >> 3) & 1u) * 4u) * 4u;

    float c[2][8][4];
#pragma unroll
    for (int mt = 0; mt < 2; mt++)
#pragma unroll
        for (int nt = 0; nt < 8; nt++)
#pragma unroll
            for (int q = 0; q < 4; q++) c[mt][nt][q] = 0.f;

    const int nch = p.K / 32;

    // ---- preload chunk 0 --------------------------------------------------
    {
        float4 av[4], bv[4];
#pragma unroll
        for (int i = 0; i < 4; i++) {
            av[i] = *reinterpret_cast<const float4*>(Ag + 4 * i);
            bv[i] = *reinterpret_cast<const float4*>(Bg + 4 * i);
        }
#pragma unroll
        for (int i = 0; i < 4; i++) {
            uint4 ua = make_uint4(f2tf32(av[i].x), f2tf32(av[i].y), f2tf32(av[i].z), f2tf32(av[i].w));
            uint4 ub = make_uint4(f2tf32(bv[i].x), f2tf32(bv[i].y), f2tf32(bv[i].z), f2tf32(bv[i].w));
            *reinterpret_cast<uint4*>(a_st + 16 * i) = ua;
            *reinterpret_cast<uint4*>(b_st + 16 * i) = ub;
        }
    }
    __syncthreads();

    for (int ck = 0; ck < nch; ++ck) {
        const int buf = ck & 1;
        const bool more = (ck + 1 < nch);
        float4 av[4], bv[4];
        if (more) {
            const float* ag = Ag + (ck + 1) * 32;
            const float* bg = Bg + (ck + 1) * 32;
#pragma unroll
            for (int i = 0; i < 4; i++) {
                av[i] = *reinterpret_cast<const float4*>(ag + 4 * i);
                bv[i] = *reinterpret_cast<const float4*>(bg + 4 * i);
            }
        }

        const uint32_t a_base = a_ld0 + (uint32_t)buf * TILE_BYTES;
        const uint32_t b_base = b_ld0 + (uint32_t)buf * TILE_BYTES;
#pragma unroll
        for (int k8 = 0; k8 < 4; k8++) {
            uint32_t a[2][4], b[4][4];
#pragma unroll
            for (int mt = 0; mt < 2; mt++)
                LDMX4(a[mt][0], a[mt][1], a[mt][2], a[mt][3],
                      a_base + (uint32_t)mt * (16u * 36u * 4u) + (uint32_t)k8 * 32u);
#pragma unroll
            for (int pr = 0; pr < 4; pr++)
                LDMX4(b[pr][0], b[pr][1], b[pr][2], b[pr][3],
                      b_base + (uint32_t)pr * (16u * 36u * 4u) + (uint32_t)k8 * 32u);
#pragma unroll
            for (int mt = 0; mt < 2; mt++)
#pragma unroll
                for (int nt = 0; nt < 8; nt++) {
                    const int pr = nt >> 1;
                    if (nt & 1) MMA_TF32(c[mt][nt], a[mt][0], a[mt][1], a[mt][2], a[mt][3],
                                         b[pr][2], b[pr][3]);
                    else        MMA_TF32(c[mt][nt], a[mt][0], a[mt][1], a[mt][2], a[mt][3],
                                         b[pr][0], b[pr][1]);
                }
        }

        if (more) {
            char* as = a_st + (buf ^ 1) * TILE_BYTES;
            char* bs = b_st + (buf ^ 1) * TILE_BYTES;
#pragma unroll
            for (int i = 0; i < 4; i++) {
                uint4 ua = make_uint4(f2tf32(av[i].x), f2tf32(av[i].y), f2tf32(av[i].z), f2tf32(av[i].w));
                uint4 ub = make_uint4(f2tf32(bv[i].x), f2tf32(bv[i].y), f2tf32(bv[i].z), f2tf32(bv[i].w));
                *reinterpret_cast<uint4*>(as + 16 * i) = ua;
                *reinterpret_cast<uint4*>(bs + 16 * i) = ub;
            }
            __syncthreads();
        }
    }

    // ---- epilogue ---------------------------------------------------------
    const int rbase = row0 + wm * 32 + (lane >> 2);
    const int cbase = col0 + wn * 64 + (lane & 3) * 2;
#pragma unroll
    for (int mt = 0; mt < 2; mt++) {
#pragma unroll
        for (int nt = 0; nt < 8; nt++) {
            const int col = cbase + nt * 8;
            float bx = 0.f, by = 0.f;
            if (p.bias) { bx = p.bias[col]; by = p.bias[col + 1]; }
#pragma unroll
            for (int h = 0; h < 2; h++) {
                const int r = rbase + mt * 16 + h * 8;
                float vx = c[mt][nt][h * 2 + 0] * alpha + bx;
                float vy = c[mt][nt][h * 2 + 1] * alpha + by;
                if (p.relu) { vx = fmaxf(vx, 0.f); vy = fmaxf(vy, 0.f); }
                *reinterpret_cast<float2*>(C + (size_t)r * p.ldc + col) = make_float2(vx, vy);
            }
        }
    }
}

// ---------------- banded logits + softmax ------------------------------------
__global__ void band_att(const float* __restrict__ Q, const float* __restrict__ Km,
                         float* __restrict__ attb, int n, int d)
{
    __shared__ __align__(16) float qs[DV];
    __shared__ float lg[BANDW];
    const int i = blockIdx.x;
    for (int c = threadIdx.x; c < d / 4; c += blockDim.x)
        *reinterpret_cast<float4*>(&qs[c * 4]) =
            *reinterpret_cast<const float4*>(Q + (size_t)i * d + c * 4);
    __syncthreads();

    const int j0 = max(i - (APP - 1), 0);
    const int j1 = min(i + (APP - 1), n - 1);
    const int nb = j1 - j0 + 1;
    const int warp = threadIdx.x >> 5, lane = threadIdx.x & 31;
    const int nwarp = blockDim.x >> 5;

    for (int jj = warp; jj < nb; jj += nwarp) {
        const float* kr = Km + (size_t)(j0 + jj) * d;
        float s = 0.f;
        for (int c = lane; c < d / 4; c += 32) {
            float4 q4 = *reinterpret_cast<const float4*>(&qs[c * 4]);
            float4 k4 = *reinterpret_cast<const float4*>(kr + c * 4);
            s = fmaf(q4.x, k4.x, s); s = fmaf(q4.y, k4.y, s);
            s = fmaf(q4.z, k4.z, s); s = fmaf(q4.w, k4.w, s);
        }
#pragma unroll
        for (int o = 16; o; o >>= 1) s += __shfl_down_sync(0xffffffffu, s, o);
        if (lane == 0) lg[jj] = s;
    }
    __syncthreads();

    if (threadIdx.x == 0) {
        float m = -1e30f;
        for (int k = 0; k < nb; k++) m = fmaxf(m, lg[k]);
        float ssum = 0.f;
        for (int k = 0; k < nb; k++) { float e = expf(lg[k] - m); lg[k] = e; ssum += e; }
        const float inv = 1.f / ssum;
        for (int k = 0; k < nb; k++) {
            const int j = j0 + k;
            attb[(size_t)i * BANDP + (j - i + (APP - 1))] = lg[k] * inv;
        }
    }
}

// ---------------- y[i] = sum_j att[j][i] * V[j] ------------------------------
__global__ void band_apply(const float* __restrict__ attb, const float* __restrict__ V,
                           float* __restrict__ Y, int n, int d)
{
    __shared__ float w[BANDW];
    const int i = blockIdx.x;
    const int j0 = max(i - (APP - 1), 0);
    const int j1 = min(i + (APP - 1), n - 1);
    const int nb = j1 - j0 + 1;
    if ((int)threadIdx.x < nb) {
        const int j = j0 + threadIdx.x;
        w[threadIdx.x] = attb[(size_t)j * BANDP + (i - j + (APP - 1))];
    }
    __syncthreads();
    for (int c = threadIdx.x; c < d / 4; c += blockDim.x) {
        float4 acc = make_float4(0.f, 0.f, 0.f, 0.f);
        for (int jj = 0; jj < nb; jj++) {
            const float wj = w[jj];
            float4 v4 = *reinterpret_cast<const float4*>(V + (size_t)(j0 + jj) * d + c * 4);
            acc.x = fmaf(wj, v4.x, acc.x); acc.y = fmaf(wj, v4.y, acc.y);
            acc.z = fmaf(wj, v4.z, acc.z); acc.w = fmaf(wj, v4.w, acc.w);
        }
        *reinterpret_cast<float4*>(Y + (size_t)i * d + c * 4) = acc;
    }
}

// ---------------- residual + layernorm ---------------------------------------
__global__ void ln_res(const float* __restrict__ y, const float* __restrict__ x,
                       const float* __restrict__ g, const float* __restrict__ b,
                       float* __restrict__ dst, int d, int dstride)
{
    __shared__ float sh1[32], sh2[32];
    __shared__ float s_mu, s_rstd;
    const int i = blockIdx.x;
    const int lane = threadIdx.x & 31, wid = threadIdx.x >> 5;
    const int nw = blockDim.x >> 5;

    float sum = 0.f, sq = 0.f;
    for (int c = threadIdx.x; c < d; c += blockDim.x) {
        float v = y[(size_t)i * d + c];
        if (x) v += x[(size_t)i * d + c];
        sum += v; sq = fmaf(v, v, sq);
    }
#pragma unroll
    for (int o = 16; o; o >>= 1) {
        sum += __shfl_down_sync(0xffffffffu, sum, o);
        sq  += __shfl_down_sync(0xffffffffu, sq,  o);
    }
    if (lane == 0) { sh1[wid] = sum; sh2[wid] = sq; }
    __syncthreads();
    if (wid == 0) {
        float s = (lane < nw) ? sh1[lane] : 0.f;
        float q = (lane < nw) ? sh2[lane] : 0.f;
#pragma unroll
        for (int o = 16; o; o >>= 1) {
            s += __shfl_down_sync(0xffffffffu, s, o);
            q += __shfl_down_sync(0xffffffffu, q, o);
        }
        if (lane == 0) {
            const float mu = s / d;
            float var = q / d - mu * mu;
            s_mu = mu;
            s_rstd = rsqrtf(var + 1e-6f);
        }
    }
    __syncthreads();
    const float mu = s_mu, rstd = s_rstd;
    for (int c = threadIdx.x; c < d; c += blockDim.x) {
        float v = y[(size_t)i * d + c];
        if (x) v += x[(size_t)i * d + c];
        dst[(size_t)i * dstride + c] = (v - mu) * rstd * g[c] + b[c];
    }
}

// ---------------- final head: sigmoid(h . kd_w + kd_b) -----------------------
__global__ void head_k(const float* __restrict__ h, const float* __restrict__ w,
                       const float* __restrict__ b, float* __restrict__ out, int d)
{
    __shared__ float sh[32];
    const int i = blockIdx.x;
    const int lane = threadIdx.x & 31, wid = threadIdx.x >> 5;
    const int nw = blockDim.x >> 5;
    float s = 0.f;
    for (int c = threadIdx.x; c < d; c += blockDim.x)
        s = fmaf(h[(size_t)i * d + c], w[c], s);
#pragma unroll
    for (int o = 16; o; o >>= 1) s += __shfl_down_sync(0xffffffffu, s, o);
    if (lane == 0) sh[wid] = s;
    __syncthreads();
    if (wid == 0) {
        float v = (lane < nw) ? sh[lane] : 0.f;
#pragma unroll
        for (int o = 16; o; o >>= 1) v += __shfl_down_sync(0xffffffffu, v, o);
        if (lane == 0) out[i] = 1.f / (1.f + expf(-(v + b[0])));
    }
}

// ---------------- scatter band attention into dense [N, 2N] output ----------
__global__ void scatter_att(const float* __restrict__ attv, const float* __restrict__ atta,
                            float* __restrict__ out, int n)
{
    const int i = blockIdx.x;
    const size_t base = (size_t)n + (size_t)i * 2u * (size_t)n;
    const int j0 = max(i - (APP - 1), 0);
    const int j1 = min(i + (APP - 1), n - 1);
    for (int k = threadIdx.x; k <= j1 - j0; k += blockDim.x) {
        const int j = j0 + k;
        const float av = attv[(size_t)i * BANDP + (j - i + (APP - 1))];
        const float aa = atta[(size_t)i * BANDP + (j - i + (APP - 1))];
        out[base + j]     = av;
        out[base + n + j] = aa;
    }
}

// ---------------- launch ------------------------------------------------------
extern "C" void kernel_launch(void* const* d_in, const int* in_sizes, int n_in,
                              void* d_out, int out_size)
{
    const float* x     = (const float*)d_in[0];
    const float* xa    = (const float*)d_in[1];
    const float* Wk_v  = (const float*)d_in[4];
    const float* Wq_v  = (const float*)d_in[5];
    const float* Wv_v  = (const float*)d_in[6];
    const float* Wo_v  = (const float*)d_in[7];
    const float* Wk_a  = (const float*)d_in[8];
    const float* Wq_a  = (const float*)d_in[9];
    const float* Wv_a  = (const float*)d_in[10];
    const float* Wo_a  = (const float*)d_in[11];
    const float* ka_w  = (const float*)d_in[12];
    const float* ka_b  = (const float*)d_in[13];
    const float* kd_w  = (const float*)d_in[14];
    const float* kd_b  = (const float*)d_in[15];
    const float* ln_y_g  = (const float*)d_in[16];
    const float* ln_y_b  = (const float*)d_in[17];
    const float* ln_ya_g = (const float*)d_in[18];
    const float* ln_ya_b = (const float*)d_in[19];
    const float* ln_ka_g = (const float*)d_in[20];
    const float* ln_ka_b = (const float*)d_in[21];

    const int n = in_sizes[0] / DV;   // 6144

    cudaFuncSetAttribute(tgemm, cudaFuncAttributeMaxDynamicSharedMemorySize, TG_SMEM);

    float *Kv, *Qv, *Vv, *Yv, *Yov, *Ka, *Qa, *Va, *Ya, *Yoa, *attv, *atta, *ycomb, *h;
    cudaGetSymbolAddress((void**)&Kv,  g_Kv);
    cudaGetSymbolAddress((void**)&Qv,  g_Qv);
    cudaGetSymbolAddress((void**)&Vv,  g_Vv);
    cudaGetSymbolAddress((void**)&Yv,  g_Yv);
    cudaGetSymbolAddress((void**)&Yov, g_Yov);
    cudaGetSymbolAddress((void**)&Ka,  g_Ka);
    cudaGetSymbolAddress((void**)&Qa,  g_Qa);
    cudaGetSymbolAddress((void**)&Va,  g_Va);
    cudaGetSymbolAddress((void**)&Ya,  g_Ya);
    cudaGetSymbolAddress((void**)&Yoa, g_Yoa);
    cudaGetSymbolAddress((void**)&attv, g_attv);
    cudaGetSymbolAddress((void**)&atta, g_atta);
    cudaGetSymbolAddress((void**)&ycomb, g_ycomb);
    cudaGetSymbolAddress((void**)&h,   g_h);

    float* out = (float*)d_out;
    const size_t full_elems = (size_t)n + 2ull * (size_t)n * (size_t)n;
    const size_t clear = ((size_t)out_size >= full_elems) ? full_elems : (size_t)out_size;
    cudaMemsetAsync(out, 0, clear * sizeof(float), 0);

    // --- video branch: batched QKV ---
    {
        TG p; p.A = x;
        p.B0 = Wk_v; p.B1 = Wq_v; p.B2 = Wv_v;
        p.C0 = Kv;   p.C1 = Qv;   p.C2 = Vv;
        p.a0 = 1.f;  p.a1 = 0.06f; p.a2 = 1.f;
        p.bias = nullptr; p.relu = 0;
        p.K = DV; p.lda = DV; p.ldb = DV; p.ldc = DV;
        tgemm<<<dim3(DV / 128, n / 128, 3), 256, TG_SMEM>>>(p);
    }
    band_att  <<<n, 256>>>(Qv, Kv, attv, n, DV);
    band_apply<<<n, 256>>>(attv, Vv, Yv, n, DV);
    {
        TG p; p.A = Yv;
        p.B0 = Wo_v; p.B1 = Wo_v; p.B2 = Wo_v;
        p.C0 = Yov;  p.C1 = Yov;  p.C2 = Yov;
        p.a0 = 1.f; p.a1 = 1.f; p.a2 = 1.f;
        p.bias = nullptr; p.relu = 0;
        p.K = DV; p.lda = DV; p.ldb = DV; p.ldc = DV;
        tgemm<<<dim3(DV / 128, n / 128, 1), 256, TG_SMEM>>>(p);
    }
    ln_res<<<n, 256>>>(Yov, x, ln_y_g, ln_y_b, ycomb, DV, DC);

    // --- audio branch: batched QKV ---
    {
        TG p; p.A = xa;
        p.B0 = Wk_a; p.B1 = Wq_a; p.B2 = Wv_a;
        p.C0 = Ka;   p.C1 = Qa;   p.C2 = Va;
        p.a0 = 1.f;  p.a1 = 0.06f; p.a2 = 1.f;
        p.bias = nullptr; p.relu = 0;
        p.K = DA; p.lda = DA; p.ldb = DA; p.ldc = DA;
        tgemm<<<dim3(DA / 128, n / 128, 3), 256, TG_SMEM>>>(p);
    }
    band_att  <<<n, 128>>>(Qa, Ka, atta, n, DA);
    band_apply<<<n, 128>>>(atta, Va, Ya, n, DA);
    {
        TG p; p.A = Ya;
        p.B0 = Wo_a; p.B1 = Wo_a; p.B2 = Wo_a;
        p.C0 = Yoa;  p.C1 = Yoa;  p.C2 = Yoa;
        p.a0 = 1.f; p.a1 = 1.f; p.a2 = 1.f;
        p.bias = nullptr; p.relu = 0;
        p.K = DA; p.lda = DA; p.ldb = DA; p.ldc = DA;
        tgemm<<<dim3(DA / 128, n / 128, 1), 256, TG_SMEM>>>(p);
    }
    ln_res<<<n, 128>>>(Yoa, xa, ln_ya_g, ln_ya_b, ycomb + DV, DA, DC);

    // --- MLP head ---
    {
        TG p; p.A = ycomb;
        p.B0 = ka_w; p.B1 = ka_w; p.B2 = ka_w;
        p.C0 = h;    p.C1 = h;    p.C2 = h;
        p.a0 = 1.f; p.a1 = 1.f; p.a2 = 1.f;
        p.bias = ka_b; p.relu = 1;
        p.K = DC; p.lda = DC; p.ldb = DC; p.ldc = DH;
        tgemm<<<dim3(DH / 128, n / 128, 1), 256, TG_SMEM>>>(p);
    }
    ln_res<<<n, 256>>>(h, nullptr, ln_ka_g, ln_ka_b, h, DH, DH);
    head_k<<<n, 256>>>(h, kd_w, kd_b, out, DH);

    // --- dense attention output ---
    if ((size_t)out_size >= full_elems)
        scatter_att<<<n, 64>>>(attv, atta, out, n);
}

// round 7
// speedup vs baseline: 6.5479x; 1.2401x over previous
#include <cuda_runtime.h>
#include <cstdint>
#include <math.h>

#define NTOK 6144
#define DV   1024
#define DA   128
#define DC   (DV + DA)   // 1152
#define DH   1024
#define APP  20
#define BANDW 39
#define BANDP 40

// ---------------- scratch (static device globals; no allocation) -------------
__device__ float g_Kv [NTOK * DV];
__device__ float g_Qv [NTOK * DV];
__device__ float g_Vv [NTOK * DV];
__device__ float g_Yv [NTOK * DV];
__device__ float g_Yov[NTOK * DV];
__device__ float g_Ka [NTOK * DA];
__device__ float g_Qa [NTOK * DA];
__device__ float g_Va [NTOK * DA];
__device__ float g_Ya [NTOK * DA];
__device__ float g_Yoa[NTOK * DA];
__device__ float g_attv[NTOK * BANDP];
__device__ float g_atta[NTOK * BANDP];
__device__ float g_ycomb[NTOK * DC];
__device__ float g_h  [NTOK * DH];

// ======================= helpers =============================================
__device__ __forceinline__ uint32_t smem_u32(const void* p) {
    uint32_t r;
    asm("{ .reg .u64 t; cvta.to.shared.u64 t, %1; cvt.u32.u64 %0, t; }"
        : "=r"(r) : "l"(p));
    return r;
}

__device__ __forceinline__ uint32_t f2tf32(float x) {
    uint32_t r;
    asm("cvt.rna.tf32.f32 %0, %1;" : "=r"(r) : "f"(x));
    return r;
}

__device__ __forceinline__ void cp16(uint32_t dst, const void* src) {
    asm volatile("cp.async.ca.shared.global [%0], [%1], 16;" :: "r"(dst), "l"(src));
}
#define CP_COMMIT() asm volatile("cp.async.commit_group;" ::: "memory")
#define CP_WAIT(n)  asm volatile("cp.async.wait_group %0;" :: "n"(n) : "memory")

#define LDMX4(r0, r1, r2, r3, addr) \
    asm volatile("ldmatrix.sync.aligned.m8n8.x4.shared.b16 {%0,%1,%2,%3}, [%4];" \
                 : "=r"(r0), "=r"(r1), "=r"(r2), "=r"(r3) : "r"(addr))

#define MMA_TF32(c, a0, a1, a2, a3, b0, b1) \
    asm volatile("mma.sync.aligned.m16n8k8.row.col.f32.tf32.tf32.f32 " \
                 "{%0,%1,%2,%3}, {%4,%5,%6,%7}, {%8,%9}, {%0,%1,%2,%3};" \
                 : "+f"((c)[0]), "+f"((c)[1]), "+f"((c)[2]), "+f"((c)[3]) \
                 : "r"(a0), "r"(a1), "r"(a2), "r"(a3), "r"(b0), "r"(b1))

#define CVT_INPLACE(r) (r) = f2tf32(__uint_as_float(r))

// =============================================================================
// tgemm: C[z] = alpha[z] * A * B[z]^T (+bias)(relu), tf32 mma + cp.async
// CTA tile 128x128, BK=32, double-buffered, 8 warps (4M x 2N).
// smem (fp32, stride 36/row): A0 A1 B0 B1, each 128x36.
// =============================================================================
struct TG {
    const float* A;
    const float *B0, *B1, *B2;
    float *C0, *C1, *C2;
    float a0, a1, a2;
    const float* bias;
    int relu;
    int K, lda, ldb, ldc;
};

#define TILE_BYTES (128 * 36 * 4)           // 18432
#define TG_SMEM    (4 * TILE_BYTES)         // 73728

__global__ void __launch_bounds__(256)
tgemm(TG p)
{
    extern __shared__ char dsm[];
    const int tid  = threadIdx.x;
    const int lane = tid & 31;
    const int wid  = tid >> 5;
    const int wm   = wid & 3;
    const int wn   = wid >> 2;

    const int row0 = blockIdx.y * 128;
    const int col0 = blockIdx.x * 128;
    const int z = blockIdx.z;
    const float* B = (z == 0) ? p.B0 : (z == 1) ? p.B1 : p.B2;
    float*       C = (z == 0) ? p.C0 : (z == 1) ? p.C1 : p.C2;
    const float alpha = (z == 0) ? p.a0 : (z == 1) ? p.a1 : p.a2;

    const uint32_t sbase = smem_u32(dsm);

    // loader mapping: 2 threads/row, 16 floats each (4 x cp16)
    const int lrow = tid >> 1;
    const int lcol = (tid & 1) * 16;
    const float* Ag = p.A + (size_t)(row0 + lrow) * p.lda + lcol;
    const float* Bg = B   + (size_t)(col0 + lrow) * p.ldb + lcol;
    const uint32_t a_stw = sbase + ((uint32_t)lrow * 36u + (uint32_t)lcol) * 4u;
    const uint32_t b_stw = a_stw + 2u * TILE_BYTES;

    const uint32_t a_ld0 = sbase +
        (((uint32_t)(wm * 32 + (lane & 15))) * 36u + ((uint32_t)(lane >> 4)) * 4u) * 4u;
    const uint32_t b_row = (uint32_t)(wn * 64 + (lane & 7) + ((lane & 16) >> 1));
    const uint32_t b_ld0 = sbase + 2u * TILE_BYTES +
        (b_row * 36u + (((uint32_t)lane >> 3) & 1u) * 4u) * 4u;

    float c[2][8][4];
#pragma unroll
    for (int mt = 0; mt < 2; mt++)
#pragma unroll
        for (int nt = 0; nt < 8; nt++)
#pragma unroll
            for (int q = 0; q < 4; q++) c[mt][nt][q] = 0.f;

    const int nch = p.K / 32;

    // prologue: chunk 0 -> buf 0
#pragma unroll
    for (int i = 0; i < 4; i++) {
        cp16(a_stw + 16u * i, Ag + 4 * i);
        cp16(b_stw + 16u * i, Bg + 4 * i);
    }
    CP_COMMIT();

    for (int ck = 0; ck < nch; ++ck) {
        const int buf = ck & 1;
        const bool more = (ck + 1 < nch);
        if (more) {
            const uint32_t off = (uint32_t)(buf ^ 1) * TILE_BYTES;
            const float* ag = Ag + (ck + 1) * 32;
            const float* bg = Bg + (ck + 1) * 32;
#pragma unroll
            for (int i = 0; i < 4; i++) {
                cp16(a_stw + off + 16u * i, ag + 4 * i);
                cp16(b_stw + off + 16u * i, bg + 4 * i);
            }
            CP_COMMIT();
        }
        if (more) CP_WAIT(1); else CP_WAIT(0);
        __syncthreads();

        const uint32_t a_base = a_ld0 + (uint32_t)buf * TILE_BYTES;
        const uint32_t b_base = b_ld0 + (uint32_t)buf * TILE_BYTES;
#pragma unroll
        for (int k8 = 0; k8 < 4; k8++) {
            uint32_t a[2][4], b[4][4];
#pragma unroll
            for (int mt = 0; mt < 2; mt++) {
                LDMX4(a[mt][0], a[mt][1], a[mt][2], a[mt][3],
                      a_base + (uint32_t)mt * (16u * 36u * 4u) + (uint32_t)k8 * 32u);
#pragma unroll
                for (int q = 0; q < 4; q++) CVT_INPLACE(a[mt][q]);
            }
#pragma unroll
            for (int pr = 0; pr < 4; pr++) {
                LDMX4(b[pr][0], b[pr][1], b[pr][2], b[pr][3],
                      b_base + (uint32_t)pr * (16u * 36u * 4u) + (uint32_t)k8 * 32u);
#pragma unroll
                for (int q = 0; q < 4; q++) CVT_INPLACE(b[pr][q]);
            }
#pragma unroll
            for (int mt = 0; mt < 2; mt++)
#pragma unroll
                for (int nt = 0; nt < 8; nt++) {
                    const int pr = nt >> 1;
                    if (nt & 1) MMA_TF32(c[mt][nt], a[mt][0], a[mt][1], a[mt][2], a[mt][3],
                                         b[pr][2], b[pr][3]);
                    else        MMA_TF32(c[mt][nt], a[mt][0], a[mt][1], a[mt][2], a[mt][3],
                                         b[pr][0], b[pr][1]);
                }
        }
        __syncthreads();
    }

    // epilogue
    const int rbase = row0 + wm * 32 + (lane >> 2);
    const int cbase = col0 + wn * 64 + (lane & 3) * 2;
#pragma unroll
    for (int mt = 0; mt < 2; mt++) {
#pragma unroll
        for (int nt = 0; nt < 8; nt++) {
            const int col = cbase + nt * 8;
            float bx = 0.f, by = 0.f;
            if (p.bias) { bx = p.bias[col]; by = p.bias[col + 1]; }
#pragma unroll
            for (int h = 0; h < 2; h++) {
                const int r = rbase + mt * 16 + h * 8;
                float vx = c[mt][nt][h * 2 + 0] * alpha + bx;
                float vy = c[mt][nt][h * 2 + 1] * alpha + by;
                if (p.relu) { vx = fmaxf(vx, 0.f); vy = fmaxf(vy, 0.f); }
                *reinterpret_cast<float2*>(C + (size_t)r * p.ldc + col) = make_float2(vx, vy);
            }
        }
    }
}

// =============================================================================
// band_att_mma: per block, 64 queries x 128 keys (j in [q0-32, q0+95]) logits
// via tf32 mma over d, then per-row band softmax -> attb.
// smem: A 64x36 x2, B 128x36 x2 (fp32); S overlays: 64 x 132.
// =============================================================================
#define BA_ATILE (64 * 36 * 4)    // 9216
#define BA_BTILE (128 * 36 * 4)   // 18432
#define BA_SMEM  (2 * BA_ATILE + 2 * BA_BTILE)  // 55296

__global__ void __launch_bounds__(256)
band_att_mma(const float* __restrict__ Q, const float* __restrict__ Km,
             float* __restrict__ attb, int n, int d)
{
    extern __shared__ char dsm[];
    const int tid  = threadIdx.x;
    const int lane = tid & 31;
    const int wid  = tid >> 5;
    const int wm   = wid & 1;    // 2 M slabs of 32
    const int wn   = wid >> 1;   // 4 N slabs of 32

    const int q0 = blockIdx.x * 64;
    const int jbase = q0 - 32;

    const uint32_t sbase = smem_u32(dsm);
    float* S = reinterpret_cast<float*>(dsm);  // overlays after mainloop

    // loaders
    const int larA = tid >> 2;                // 0..63
    const int lacA = (tid & 3) * 8;           // 0,8,16,24
    const int larB = tid >> 1;                // 0..127
    const int lacB = (tid & 1) * 16;
    const int jB   = min(max(jbase + larB, 0), n - 1);
    const float* Qg = Q  + (size_t)(q0 + larA) * d + lacA;
    const float* Kg = Km + (size_t)jB * d + lacB;
    const uint32_t a_stw = sbase + ((uint32_t)larA * 36u + (uint32_t)lacA) * 4u;
    const uint32_t b_stw = sbase + 2u * BA_ATILE +
                           ((uint32_t)larB * 36u + (uint32_t)lacB) * 4u;

    const uint32_t a_ld0 = sbase +
        (((uint32_t)(wm * 32 + (lane & 15))) * 36u + ((uint32_t)(lane >> 4)) * 4u) * 4u;
    const uint32_t b_row = (uint32_t)(wn * 32 + (lane & 7) + ((lane & 16) >> 1));
    const uint32_t b_ld0 = sbase + 2u * BA_ATILE +
        (b_row * 36u + (((uint32_t)lane >> 3) & 1u) * 4u) * 4u;

    float c[2][4][4];
#pragma unroll
    for (int mt = 0; mt < 2; mt++)
#pragma unroll
        for (int nt = 0; nt < 4; nt++)
#pragma unroll
            for (int q = 0; q < 4; q++) c[mt][nt][q] = 0.f;

    const int nch = d / 32;

    // prologue
#pragma unroll
    for (int i = 0; i < 2; i++) cp16(a_stw + 16u * i, Qg + 4 * i);
#pragma unroll
    for (int i = 0; i < 4; i++) cp16(b_stw + 16u * i, Kg + 4 * i);
    CP_COMMIT();

    for (int ck = 0; ck < nch; ++ck) {
        const int buf = ck & 1;
        const bool more = (ck + 1 < nch);
        if (more) {
            const float* qg = Qg + (ck + 1) * 32;
            const float* kg = Kg + (ck + 1) * 32;
            const uint32_t ao = (uint32_t)(buf ^ 1) * BA_ATILE;
            const uint32_t bo = (uint32_t)(buf ^ 1) * BA_BTILE;
#pragma unroll
            for (int i = 0; i < 2; i++) cp16(a_stw + ao + 16u * i, qg + 4 * i);
#pragma unroll
            for (int i = 0; i < 4; i++) cp16(b_stw + bo + 16u * i, kg + 4 * i);
            CP_COMMIT();
        }
        if (more) CP_WAIT(1); else CP_WAIT(0);
        __syncthreads();

        const uint32_t a_base = a_ld0 + (uint32_t)buf * BA_ATILE;
        const uint32_t b_base = b_ld0 + (uint32_t)buf * BA_BTILE;
#pragma unroll
        for (int k8 = 0; k8 < 4; k8++) {
            uint32_t a[2][4], b[2][4];
#pragma unroll
            for (int mt = 0; mt < 2; mt++) {
                LDMX4(a[mt][0], a[mt][1], a[mt][2], a[mt][3],
                      a_base + (uint32_t)mt * (16u * 36u * 4u) + (uint32_t)k8 * 32u);
#pragma unroll
                for (int q = 0; q < 4; q++) CVT_INPLACE(a[mt][q]);
            }
#pragma unroll
            for (int pr = 0; pr < 2; pr++) {
                LDMX4(b[pr][0], b[pr][1], b[pr][2], b[pr][3],
                      b_base + (uint32_t)pr * (16u * 36u * 4u) + (uint32_t)k8 * 32u);
#pragma unroll
                for (int q = 0; q < 4; q++) CVT_INPLACE(b[pr][q]);
            }
#pragma unroll
            for (int mt = 0; mt < 2; mt++)
#pragma unroll
                for (int nt = 0; nt < 4; nt++) {
                    const int pr = nt >> 1;
                    if (nt & 1) MMA_TF32(c[mt][nt], a[mt][0], a[mt][1], a[mt][2], a[mt][3],
                                         b[pr][2], b[pr][3]);
                    else        MMA_TF32(c[mt][nt], a[mt][0], a[mt][1], a[mt][2], a[mt][3],
                                         b[pr][0], b[pr][1]);
                }
        }
        __syncthreads();
    }

    // store logits into S[64][132]
#pragma unroll
    for (int mt = 0; mt < 2; mt++)
#pragma unroll
        for (int nt = 0; nt < 4; nt++)
#pragma unroll
            for (int h = 0; h < 2; h++) {
                const int r = wm * 32 + mt * 16 + (lane >> 2) + h * 8;
                const int cc = wn * 32 + nt * 8 + (lane & 3) * 2;
                S[r * 132 + cc]     = c[mt][nt][h * 2 + 0];
                S[r * 132 + cc + 1] = c[mt][nt][h * 2 + 1];
            }
    __syncthreads();

    // band softmax: warp handles 8 rows, 4 lanes per row, 10 slots per lane
    const int i = wid * 8 + (lane >> 2);
    const int sl = lane & 3;
    float vals[10];
    float m = -1e30f;
#pragma unroll
    for (int k = 0; k < 10; k++) {
        const int s = sl + 4 * k;
        float v = -1e30f;
        if (s < BANDW) {
            const int j = q0 + i + s - (APP - 1);
            if (j >= 0 && j < n) v = S[i * 132 + (i + 13 + s)];
        }
        vals[k] = v;
        m = fmaxf(m, v);
    }
    m = fmaxf(m, __shfl_xor_sync(0xffffffffu, m, 1));
    m = fmaxf(m, __shfl_xor_sync(0xffffffffu, m, 2));
    float sum = 0.f;
#pragma unroll
    for (int k = 0; k < 10; k++) {
        const float e = expf(vals[k] - m);
        vals[k] = e;
        sum += e;
    }
    sum += __shfl_xor_sync(0xffffffffu, sum, 1);
    sum += __shfl_xor_sync(0xffffffffu, sum, 2);
    const float inv = 1.f / sum;
#pragma unroll
    for (int k = 0; k < 10; k++) {
        const int s = sl + 4 * k;
        if (s < BANDW)
            attb[(size_t)(q0 + i) * BANDP + s] = vals[k] * inv;
    }
}

// =============================================================================
// band_apply tiled: 64 outputs/block.  y[i] = sum_s ws[i][s] * V[i+s-19]
// ws[i][s] = attb[j][38-s], j = i+s-19.  V staged in smem, 128-col chunks.
// smem: ws[64][40] @0 (10240B), Vs[104][128] @10240 (53248B) -> 63488B.
// =============================================================================
#define BP_SMEM 63488

__global__ void __launch_bounds__(256)
band_apply_t(const float* __restrict__ attb, const float* __restrict__ V,
             float* __restrict__ Y, int n, int d)
{
    extern __shared__ char dsm[];
    float* ws = reinterpret_cast<float*>(dsm);            // [64][40]
    float* Vs = reinterpret_cast<float*>(dsm + 10240);    // [104][128]

    const int tid = threadIdx.x;
    const int q0 = blockIdx.x * 64;
    const int jbase = q0 - (APP - 1);

    // load weights (transposed band gather)
    for (int idx = tid; idx < 64 * BANDW; idx += 256) {
        const int i = idx / BANDW;
        const int s = idx - i * BANDW;
        const int j = q0 + i + s - (APP - 1);
        float w = 0.f;
        if (j >= 0 && j < n) w = attb[(size_t)j * BANDP + (38 - s)];
        ws[i * 40 + s] = w;
    }

    const int qg = tid >> 5;     // 0..7
    const int cg = tid & 31;     // 0..31
    const int nchunk = d / 128;

    for (int ch = 0; ch < nchunk; ++ch) {
        __syncthreads();
        // load V rows [jbase, jbase+102), cols [ch*128, ch*128+128)
        for (int idx = tid; idx < 102 * 32; idx += 256) {
            const int row = idx >> 5;
            const int c4  = idx & 31;
            const int j = min(max(jbase + row, 0), n - 1);
            *reinterpret_cast<float4*>(&Vs[row * 128 + c4 * 4]) =
                *reinterpret_cast<const float4*>(V + (size_t)j * d + ch * 128 + c4 * 4);
        }
        __syncthreads();

        float4 acc[8];
#pragma unroll
        for (int q = 0; q < 8; q++) acc[q] = make_float4(0.f, 0.f, 0.f, 0.f);

#pragma unroll
        for (int r = 0; r <= 45; r++) {
            const float4 v4 = *reinterpret_cast<const float4*>(&Vs[(qg * 8 + r) * 128 + cg * 4]);
#pragma unroll
            for (int q = 0; q < 8; q++) {
                const int s = r - q;
                if (s >= 0 && s < BANDW) {
                    const float w = ws[(qg * 8 + q) * 40 + s];
                    acc[q].x = fmaf(w, v4.x, acc[q].x);
                    acc[q].y = fmaf(w, v4.y, acc[q].y);
                    acc[q].z = fmaf(w, v4.z, acc[q].z);
                    acc[q].w = fmaf(w, v4.w, acc[q].w);
                }
            }
        }
#pragma unroll
        for (int q = 0; q < 8; q++) {
            const int i = q0 + qg * 8 + q;
            *reinterpret_cast<float4*>(Y + (size_t)i * d + ch * 128 + cg * 4) = acc[q];
        }
    }
}

// ---------------- residual + layernorm ---------------------------------------
__global__ void ln_res(const float* __restrict__ y, const float* __restrict__ x,
                       const float* __restrict__ g, const float* __restrict__ b,
                       float* __restrict__ dst, int d, int dstride)
{
    __shared__ float sh1[32], sh2[32];
    __shared__ float s_mu, s_rstd;
    const int i = blockIdx.x;
    const int lane = threadIdx.x & 31, wid = threadIdx.x >> 5;
    const int nw = blockDim.x >> 5;

    float sum = 0.f, sq = 0.f;
    for (int c = threadIdx.x; c < d; c += blockDim.x) {
        float v = y[(size_t)i * d + c];
        if (x) v += x[(size_t)i * d + c];
        sum += v; sq = fmaf(v, v, sq);
    }
#pragma unroll
    for (int o = 16; o; o >>= 1) {
        sum += __shfl_down_sync(0xffffffffu, sum, o);
        sq  += __shfl_down_sync(0xffffffffu, sq,  o);
    }
    if (lane == 0) { sh1[wid] = sum; sh2[wid] = sq; }
    __syncthreads();
    if (wid == 0) {
        float s = (lane < nw) ? sh1[lane] : 0.f;
        float q = (lane < nw) ? sh2[lane] : 0.f;
#pragma unroll
        for (int o = 16; o; o >>= 1) {
            s += __shfl_down_sync(0xffffffffu, s, o);
            q += __shfl_down_sync(0xffffffffu, q, o);
        }
        if (lane == 0) {
            const float mu = s / d;
            float var = q / d - mu * mu;
            s_mu = mu;
            s_rstd = rsqrtf(var + 1e-6f);
        }
    }
    __syncthreads();
    const float mu = s_mu, rstd = s_rstd;
    for (int c = threadIdx.x; c < d; c += blockDim.x) {
        float v = y[(size_t)i * d + c];
        if (x) v += x[(size_t)i * d + c];
        dst[(size_t)i * dstride + c] = (v - mu) * rstd * g[c] + b[c];
    }
}

// ---------------- final head -------------------------------------------------
__global__ void head_k(const float* __restrict__ h, const float* __restrict__ w,
                       const float* __restrict__ b, float* __restrict__ out, int d)
{
    __shared__ float sh[32];
    const int i = blockIdx.x;
    const int lane = threadIdx.x & 31, wid = threadIdx.x >> 5;
    const int nw = blockDim.x >> 5;
    float s = 0.f;
    for (int c = threadIdx.x; c < d; c += blockDim.x)
        s = fmaf(h[(size_t)i * d + c], w[c], s);
#pragma unroll
    for (int o = 16; o; o >>= 1) s += __shfl_down_sync(0xffffffffu, s, o);
    if (lane == 0) sh[wid] = s;
    __syncthreads();
    if (wid == 0) {
        float v = (lane < nw) ? sh[lane] : 0.f;
#pragma unroll
        for (int o = 16; o; o >>= 1) v += __shfl_down_sync(0xffffffffu, v, o);
        if (lane == 0) out[i] = 1.f / (1.f + expf(-(v + b[0])));
    }
}

// ---------------- scatter band attention into dense [N, 2N] output ----------
__global__ void scatter_att(const float* __restrict__ attv, const float* __restrict__ atta,
                            float* __restrict__ out, int n)
{
    const int i = blockIdx.x;
    const size_t base = (size_t)n + (size_t)i * 2u * (size_t)n;
    const int j0 = max(i - (APP - 1), 0);
    const int j1 = min(i + (APP - 1), n - 1);
    for (int k = threadIdx.x; k <= j1 - j0; k += blockDim.x) {
        const int j = j0 + k;
        const float av = attv[(size_t)i * BANDP + (j - i + (APP - 1))];
        const float aa = atta[(size_t)i * BANDP + (j - i + (APP - 1))];
        out[base + j]     = av;
        out[base + n + j] = aa;
    }
}

// ---------------- launch ------------------------------------------------------
extern "C" void kernel_launch(void* const* d_in, const int* in_sizes, int n_in,
                              void* d_out, int out_size)
{
    const float* x     = (const float*)d_in[0];
    const float* xa    = (const float*)d_in[1];
    const float* Wk_v  = (const float*)d_in[4];
    const float* Wq_v  = (const float*)d_in[5];
    const float* Wv_v  = (const float*)d_in[6];
    const float* Wo_v  = (const float*)d_in[7];
    const float* Wk_a  = (const float*)d_in[8];
    const float* Wq_a  = (const float*)d_in[9];
    const float* Wv_a  = (const float*)d_in[10];
    const float* Wo_a  = (const float*)d_in[11];
    const float* ka_w  = (const float*)d_in[12];
    const float* ka_b  = (const float*)d_in[13];
    const float* kd_w  = (const float*)d_in[14];
    const float* kd_b  = (const float*)d_in[15];
    const float* ln_y_g  = (const float*)d_in[16];
    const float* ln_y_b  = (const float*)d_in[17];
    const float* ln_ya_g = (const float*)d_in[18];
    const float* ln_ya_b = (const float*)d_in[19];
    const float* ln_ka_g = (const float*)d_in[20];
    const float* ln_ka_b = (const float*)d_in[21];

    const int n = in_sizes[0] / DV;   // 6144

    cudaFuncSetAttribute(tgemm, cudaFuncAttributeMaxDynamicSharedMemorySize, TG_SMEM);
    cudaFuncSetAttribute(band_att_mma, cudaFuncAttributeMaxDynamicSharedMemorySize, BA_SMEM);
    cudaFuncSetAttribute(band_apply_t, cudaFuncAttributeMaxDynamicSharedMemorySize, BP_SMEM);

    float *Kv, *Qv, *Vv, *Yv, *Yov, *Ka, *Qa, *Va, *Ya, *Yoa, *attv, *atta, *ycomb, *h;
    cudaGetSymbolAddress((void**)&Kv,  g_Kv);
    cudaGetSymbolAddress((void**)&Qv,  g_Qv);
    cudaGetSymbolAddress((void**)&Vv,  g_Vv);
    cudaGetSymbolAddress((void**)&Yv,  g_Yv);
    cudaGetSymbolAddress((void**)&Yov, g_Yov);
    cudaGetSymbolAddress((void**)&Ka,  g_Ka);
    cudaGetSymbolAddress((void**)&Qa,  g_Qa);
    cudaGetSymbolAddress((void**)&Va,  g_Va);
    cudaGetSymbolAddress((void**)&Ya,  g_Ya);
    cudaGetSymbolAddress((void**)&Yoa, g_Yoa);
    cudaGetSymbolAddress((void**)&attv, g_attv);
    cudaGetSymbolAddress((void**)&atta, g_atta);
    cudaGetSymbolAddress((void**)&ycomb, g_ycomb);
    cudaGetSymbolAddress((void**)&h,   g_h);

    float* out = (float*)d_out;
    const size_t full_elems = (size_t)n + 2ull * (size_t)n * (size_t)n;
    const size_t clear = ((size_t)out_size >= full_elems) ? full_elems : (size_t)out_size;
    cudaMemsetAsync(out, 0, clear * sizeof(float), 0);

    const int nb = n / 64;   // 96 band blocks

    // --- video branch ---
    {
        TG p; p.A = x;
        p.B0 = Wk_v; p.B1 = Wq_v; p.B2 = Wv_v;
        p.C0 = Kv;   p.C1 = Qv;   p.C2 = Vv;
        p.a0 = 1.f;  p.a1 = 0.06f; p.a2 = 1.f;
        p.bias = nullptr; p.relu = 0;
        p.K = DV; p.lda = DV; p.ldb = DV; p.ldc = DV;
        tgemm<<<dim3(DV / 128, n / 128, 3), 256, TG_SMEM>>>(p);
    }
    band_att_mma<<<nb, 256, BA_SMEM>>>(Qv, Kv, attv, n, DV);
    band_apply_t<<<nb, 256, BP_SMEM>>>(attv, Vv, Yv, n, DV);
    {
        TG p; p.A = Yv;
        p.B0 = Wo_v; p.B1 = Wo_v; p.B2 = Wo_v;
        p.C0 = Yov;  p.C1 = Yov;  p.C2 = Yov;
        p.a0 = 1.f; p.a1 = 1.f; p.a2 = 1.f;
        p.bias = nullptr; p.relu = 0;
        p.K = DV; p.lda = DV; p.ldb = DV; p.ldc = DV;
        tgemm<<<dim3(DV / 128, n / 128, 1), 256, TG_SMEM>>>(p);
    }
    ln_res<<<n, 256>>>(Yov, x, ln_y_g, ln_y_b, ycomb, DV, DC);

    // --- audio branch ---
    {
        TG p; p.A = xa;
        p.B0 = Wk_a; p.B1 = Wq_a; p.B2 = Wv_a;
        p.C0 = Ka;   p.C1 = Qa;   p.C2 = Va;
        p.a0 = 1.f;  p.a1 = 0.06f; p.a2 = 1.f;
        p.bias = nullptr; p.relu = 0;
        p.K = DA; p.lda = DA; p.ldb = DA; p.ldc = DA;
        tgemm<<<dim3(DA / 128, n / 128, 3), 256, TG_SMEM>>>(p);
    }
    band_att_mma<<<nb, 256, BA_SMEM>>>(Qa, Ka, atta, n, DA);
    band_apply_t<<<nb, 256, BP_SMEM>>>(atta, Va, Ya, n, DA);
    {
        TG p; p.A = Ya;
        p.B0 = Wo_a; p.B1 = Wo_a; p.B2 = Wo_a;
        p.C0 = Yoa;  p.C1 = Yoa;  p.C2 = Yoa;
        p.a0 = 1.f; p.a1 = 1.f; p.a2 = 1.f;
        p.bias = nullptr; p.relu = 0;
        p.K = DA; p.lda = DA; p.ldb = DA; p.ldc = DA;
        tgemm<<<dim3(DA / 128, n / 128, 1), 256, TG_SMEM>>>(p);
    }
    ln_res<<<n, 128>>>(Yoa, xa, ln_ya_g, ln_ya_b, ycomb + DV, DA, DC);

    // --- MLP head ---
    {
        TG p; p.A = ycomb;
        p.B0 = ka_w; p.B1 = ka_w; p.B2 = ka_w;
        p.C0 = h;    p.C1 = h;    p.C2 = h;
        p.a0 = 1.f; p.a1 = 1.f; p.a2 = 1.f;
        p.bias = ka_b; p.relu = 1;
        p.K = DC; p.lda = DC; p.ldb = DC; p.ldc = DH;
        tgemm<<<dim3(DH / 128, n / 128, 1), 256, TG_SMEM>>>(p);
    }
    ln_res<<<n, 256>>>(h, nullptr, ln_ka_g, ln_ka_b, h, DH, DH);
    head_k<<<n, 256>>>(h, kd_w, kd_b, out, DH);

    // --- dense attention output ---
    if ((size_t)out_size >= full_elems)
        scatter_att<<<n, 64>>>(attv, atta, out, n);
}